// round 16
// baseline (speedup 1.0000x reference)
#include <cuda_runtime.h>
#include <mma.h>
#include <cstdint>
using namespace nvcuda;
#define B_ 32
#define C_ 128
#define P_ 4096
#define PI_ 3.14159265358979323846f

__device__ float  g_xc[B_*C_*P_];
__device__ float  g_xl[B_*256*P_];
__device__ float  g_xo[B_*C_*P_];
__device__ float  g_cA[B_*256*P_];
__device__ float  g_we[C_*P_];
__device__ float  g_weS[65*P_];
__device__ float  g_wn[4096];
__device__ float2 g_F64[4096];
__device__ float  g_WCf[128*128];
__device__ float  g_WCi[128*128];
__device__ float  g_WCf2[128*128];
__device__ float  g_bFf[128];
__device__ float  g_meanxc[B_*C_];
__device__ float  g_h1[B_*256];
__device__ int    g_expert[B_];

__device__ __forceinline__ float t32(float v){return wmma::__float_to_tf32(v);}

__global__ void k_consts(){
  int i=blockIdx.x*256+threadIdx.x;
  if(i<4096){
    int n=i>>6,h=i&63;
    float v=cospif((float)n*(h+0.5f)/64.f)*sqrtf(2.f/64.f);
    if(n==0)v*=0.70710678118654752f;
    g_wn[i]=v;
    float a=(float)((n*h)&63)/32.f;
    g_F64[i]=make_float2(cospif(a),-sinpif(a));
  }
  if(i<16384){
    int r=i>>7, j=i&127;
    if(r<=64){
      g_WCf[i]=cospif((float)((r*j)&127)/64.f);
    }else{
      int k=r-64;
      g_WCf[i]=-sinpif((float)((k*j)&127)/64.f);
    }
    int c=r;
    if(j<=64){
      float s=(j==0||j==64)?1.f:2.f;
      g_WCi[c*128+j]=s*cospif((float)((j*c)&127)/64.f)*(1.f/128.f);
    }else{
      int k=j-64;
      g_WCi[c*128+j]=-2.f*sinpif((float)((k*c)&127)/64.f)*(1.f/128.f);
    }
  }
}

__global__ __launch_bounds__(128) void k_combine(const float* __restrict__ lw,
    const float* __restrict__ lb){
  __shared__ float srow[128];
  int r=blockIdx.x, t=threadIdx.x;
  srow[t]=g_WCf[r*128+t];
  __syncthreads();
  float a=0.f;
  #pragma unroll 4
  for(int j=0;j<128;j++) a+=srow[j]*__ldg(lw+j*128+t);
  g_WCf2[r*128+t]=a;
  if(t==0){
    float bsum=0.f;
    for(int j=0;j<128;j++) bsum+=srow[j]*__ldg(lb+j);
    g_bFf[r]=bsum;
  }
}

__global__ __launch_bounds__(256) void k_we(const float* __restrict__ fe,
    const float* __restrict__ tw,const float* __restrict__ tb){
  __shared__ float sfe[128*33];
  __shared__ float stw[128*32];
  int t=threadIdx.x,p0=blockIdx.x*32;
  for(int idx=t;idx<4096;idx+=256){int pl=idx>>7,c=idx&127;sfe[c*33+pl]=fe[(p0+pl)*128+c];}
  int pl=t&31,cg=t>>5;
  int p=p0+pl,h=p>>6,w=p&63;
  float s=(PI_*PI_/4096.f)*(float)(h*h+w*w);
  float acc[16];
  #pragma unroll
  for(int i=0;i<16;i++)acc[i]=0.f;
  for(int ct=0;ct<4;ct++){
    __syncthreads();
    for(int idx=t;idx<4096;idx+=256){
      int o=idx>>5, cc=idx&31;
      stw[o*32+cc]=tw[o*128+ct*32+cc];
    }
    __syncthreads();
    #pragma unroll
    for(int cc=0;cc<32;cc++){
      float f=sfe[(ct*32+cc)*33+pl];
      #pragma unroll
      for(int i=0;i<16;i++)acc[i]+=f*stw[(cg*16+i)*32+cc];
    }
  }
  #pragma unroll
  for(int i=0;i<16;i++){
    int c=cg*16+i;
    float k=fmaxf(acc[i]+__ldg(tb+c),0.f);
    g_we[c*P_+p]=expf(-s*k);
  }
}

__global__ void k_weS(){
  int ki=blockIdx.x;
  for(int p=threadIdx.x;p<4096;p+=256){
    int fh=p>>6, fw=p&63;
    int kn=(128-ki)&127, hn=(64-fh)&63, wn=(64-fw)&63;
    g_weS[ki*P_+p]=0.5f*(g_we[ki*P_+p]+g_we[kn*P_+hn*64+wn]);
  }
}

__global__ __launch_bounds__(256) void k_conv(const float* __restrict__ x,
    const float* __restrict__ wt,const float* __restrict__ bs){
  int c=blockIdx.x,b=blockIdx.y;
  __shared__ float sT[66*72];
  __shared__ float red[256];
  int t=threadIdx.x;
  const float* xp=x+(size_t)(b*C_+c)*P_;
  for(int i=t;i<66*72;i+=256) sT[i]=0.f;
  __syncthreads();
  #pragma unroll
  for(int i=0;i<4;i++){
    int vidx=t+i*256;
    int r=vidx>>4, cq=vidx&15;
    float4 v=*(const float4*)(xp+r*64+cq*4);
    *(float4*)&sT[(r+1)*72+4+cq*4]=v;
  }
  __syncthreads();
  const float* wc=wt+c*9;
  float w0=__ldg(wc+0),w1=__ldg(wc+1),w2=__ldg(wc+2),
        w3=__ldg(wc+3),w4=__ldg(wc+4),w5=__ldg(wc+5),
        w6=__ldg(wc+6),w7=__ldg(wc+7),w8=__ldg(wc+8);
  float bb=__ldg(bs+c);
  float tot=0.f;
  float* op=g_xc+(size_t)(b*C_+c)*P_;
  #pragma unroll
  for(int i=0;i<16;i++){
    int p=t+i*256; int r=p>>6, cl=p&63;
    const float* s=&sT[r*72+cl+3];
    float acc=bb + w0*s[0]+w1*s[1]+w2*s[2]
                 + w3*s[72]+w4*s[73]+w5*s[74]
                 + w6*s[144]+w7*s[145]+w8*s[146];
    op[p]=acc; tot+=acc;
  }
  red[t]=tot; __syncthreads();
  for(int st=128;st>0;st>>=1){if(t<st)red[t]+=red[t+st];__syncthreads();}
  if(t==0) g_meanxc[b*128+c]=red[0]*(1.f/4096.f);
}

// TF32 tensor gemm, double-buffered with register prefetch. K must be 128.
// gate>=0: expert==gate; gate==-1: all; gate==-2: expert!=1.
__global__ __launch_bounds__(256) void k_gemm(const float* __restrict__ in, size_t inBS, int K,
    const float* __restrict__ W,const float* __restrict__ bias,
    float* __restrict__ out, size_t outBS, int gate){
  int b=blockIdx.z;
  if(gate>=0 && g_expert[b]!=gate)return;
  if(gate==-2 && g_expert[b]==1)return;
  __shared__ __align__(32) float sA[2][64*36];
  __shared__ __align__(32) float sB[2][32*68];
  int t=threadIdx.x, m0=blockIdx.y*64, p0=blockIdx.x*64;
  int warp=t>>5, mt=warp&3, nh=warp>>2;
  int am=t>>2, ak=(t&3)*8;
  int bk=t>>3, bp=(t&7)*8;
  const float* X=in+(size_t)b*inBS;

  wmma::fragment<wmma::accumulator,16,16,8,float> c0,c1;
  wmma::fill_fragment(c0,0.f); wmma::fill_fragment(c1,0.f);
  wmma::fragment<wmma::matrix_a,16,16,8,wmma::precision::tf32,wmma::row_major> af;
  wmma::fragment<wmma::matrix_b,16,16,8,wmma::precision::tf32,wmma::row_major> bf0,bf1;

  float4 a0=*(const float4*)(W+(size_t)(m0+am)*K+ak);
  float4 a1=*(const float4*)(W+(size_t)(m0+am)*K+ak+4);
  float4 b0v=*(const float4*)(X+(size_t)bk*P_+p0+bp);
  float4 b1v=*(const float4*)(X+(size_t)bk*P_+p0+bp+4);
  {
    float* d=&sA[0][am*36+ak];
    d[0]=t32(a0.x);d[1]=t32(a0.y);d[2]=t32(a0.z);d[3]=t32(a0.w);
    d[4]=t32(a1.x);d[5]=t32(a1.y);d[6]=t32(a1.z);d[7]=t32(a1.w);
    float* e=&sB[0][bk*68+bp];
    e[0]=t32(b0v.x);e[1]=t32(b0v.y);e[2]=t32(b0v.z);e[3]=t32(b0v.w);
    e[4]=t32(b1v.x);e[5]=t32(b1v.y);e[6]=t32(b1v.z);e[7]=t32(b1v.w);
  }
  __syncthreads();
  #pragma unroll
  for(int kt=0;kt<4;kt++){
    int cur=kt&1;
    bool more=(kt<3);
    if(more){
      a0=*(const float4*)(W+(size_t)(m0+am)*K+(kt+1)*32+ak);
      a1=*(const float4*)(W+(size_t)(m0+am)*K+(kt+1)*32+ak+4);
      b0v=*(const float4*)(X+(size_t)((kt+1)*32+bk)*P_+p0+bp);
      b1v=*(const float4*)(X+(size_t)((kt+1)*32+bk)*P_+p0+bp+4);
    }
    #pragma unroll
    for(int kk=0;kk<4;kk++){
      wmma::load_matrix_sync(af,&sA[cur][mt*16*36+kk*8],36);
      wmma::load_matrix_sync(bf0,&sB[cur][kk*8*68+nh*32],68);
      wmma::load_matrix_sync(bf1,&sB[cur][kk*8*68+nh*32+16],68);
      wmma::mma_sync(c0,af,bf0,c0);
      wmma::mma_sync(c1,af,bf1,c1);
    }
    if(more){
      int nxt=cur^1;
      float* d=&sA[nxt][am*36+ak];
      d[0]=t32(a0.x);d[1]=t32(a0.y);d[2]=t32(a0.z);d[3]=t32(a0.w);
      d[4]=t32(a1.x);d[5]=t32(a1.y);d[6]=t32(a1.z);d[7]=t32(a1.w);
      float* e=&sB[nxt][bk*68+bp];
      e[0]=t32(b0v.x);e[1]=t32(b0v.y);e[2]=t32(b0v.z);e[3]=t32(b0v.w);
      e[4]=t32(b1v.x);e[5]=t32(b1v.y);e[6]=t32(b1v.z);e[7]=t32(b1v.w);
    }
    __syncthreads();
  }
  // epilogue: reuse sA (2*2304=4608 floats >= 64*68=4352)
  float* sC=&sA[0][0];
  wmma::store_matrix_sync(&sC[mt*16*68+nh*32],c0,68,wmma::mem_row_major);
  wmma::store_matrix_sync(&sC[mt*16*68+nh*32+16],c1,68,wmma::mem_row_major);
  __syncthreads();
  {
    int m=t>>2, pq=(t&3)*16;
    float bb=bias?__ldg(bias+m0+m):0.f;
    float* op=out+(size_t)b*outBS+(size_t)(m0+m)*P_+p0+pq;
    #pragma unroll
    for(int j=0;j<16;j+=4){
      float4 v=*(float4*)&sC[m*68+pq+j];
      v.x+=bb;v.y+=bb;v.z+=bb;v.w+=bb;
      *(float4*)(op+j)=v;
    }
  }
}

// fused LN + silu-gate + final gemm, TF32 wmma mainloop.
__global__ __launch_bounds__(256) void k_lngemm(
    const float* __restrict__ W,const float* __restrict__ bias,
    const float* __restrict__ og,const float* __restrict__ ob,
    float* __restrict__ out,int gate){
  int b=blockIdx.z;
  if(g_expert[b]!=gate)return;
  __shared__ __align__(32) float sm[4480];   // sA 64x36 @0 (2304) + sB 32x68 @2304 (2176); sC reuse @0
  __shared__ float part[256],part2[256];
  __shared__ float smu[64],srs[64];
  int m0=blockIdx.y*64,p0=blockIdx.x*64,t=threadIdx.x;
  int warp=t>>5, mt=warp&3, nh=warp>>2;
  int am=t>>2, ak=(t&3)*8;
  int bk=t>>3, bp=(t&7)*8;
  float* sA=sm; float* sB=sm+2304;
  // stats
  {
    int p=t&63,q=t>>6;
    float s=0.f,s2=0.f;
    for(int c=q*32;c<q*32+32;c++){
      float v=g_xo[(size_t)(b*C_+c)*P_+p0+p];
      s+=v;s2+=v*v;
    }
    part[t]=s;part2[t]=s2;
  }
  __syncthreads();
  if(t<64){
    float S=part[t]+part[t+64]+part[t+128]+part[t+192];
    float S2=part2[t]+part2[t+64]+part2[t+128]+part2[t+192];
    float m=S*(1.f/128.f);
    smu[t]=m;
    srs[t]=rsqrtf(fmaxf(S2*(1.f/128.f)-m*m,0.f)+1e-5f);
  }
  __syncthreads();
  wmma::fragment<wmma::accumulator,16,16,8,float> c0,c1;
  wmma::fill_fragment(c0,0.f); wmma::fill_fragment(c1,0.f);
  wmma::fragment<wmma::matrix_a,16,16,8,wmma::precision::tf32,wmma::row_major> af;
  wmma::fragment<wmma::matrix_b,16,16,8,wmma::precision::tf32,wmma::row_major> bf0,bf1;
  for(int kt=0;kt<4;kt++){
    {
      float4 a0=*(const float4*)(W+(size_t)(m0+am)*128+kt*32+ak);
      float4 a1=*(const float4*)(W+(size_t)(m0+am)*128+kt*32+ak+4);
      float* d=&sA[am*36+ak];
      d[0]=t32(a0.x);d[1]=t32(a0.y);d[2]=t32(a0.z);d[3]=t32(a0.w);
      d[4]=t32(a1.x);d[5]=t32(a1.y);d[6]=t32(a1.z);d[7]=t32(a1.w);
    }
    {
      int c=kt*32+bk;
      const float* xo=g_xo+(size_t)(b*C_+c)*P_+p0+bp;
      const float* zz=g_xl+(size_t)(b*256+128+c)*P_+p0+bp;
      float4 x0=*(const float4*)xo, x1=*(const float4*)(xo+4);
      float4 z0=*(const float4*)zz, z1=*(const float4*)(zz+4);
      float gg=__ldg(og+c), bo=__ldg(ob+c);
      float* e=&sB[bk*68+bp];
      float xv[8]={x0.x,x0.y,x0.z,x0.w,x1.x,x1.y,x1.z,x1.w};
      float zv[8]={z0.x,z0.y,z0.z,z0.w,z1.x,z1.y,z1.z,z1.w};
      #pragma unroll
      for(int j=0;j<8;j++){
        int p=bp+j;
        float y=((xv[j]-smu[p])*srs[p]*gg+bo)*(zv[j]/(1.f+expf(-zv[j])));
        e[j]=t32(y);
      }
    }
    __syncthreads();
    #pragma unroll
    for(int kk=0;kk<4;kk++){
      wmma::load_matrix_sync(af,&sA[mt*16*36+kk*8],36);
      wmma::load_matrix_sync(bf0,&sB[kk*8*68+nh*32],68);
      wmma::load_matrix_sync(bf1,&sB[kk*8*68+nh*32+16],68);
      wmma::mma_sync(c0,af,bf0,c0);
      wmma::mma_sync(c1,af,bf1,c1);
    }
    __syncthreads();
  }
  float* sC=sm;
  wmma::store_matrix_sync(&sC[mt*16*68+nh*32],c0,68,wmma::mem_row_major);
  wmma::store_matrix_sync(&sC[mt*16*68+nh*32+16],c1,68,wmma::mem_row_major);
  __syncthreads();
  {
    int m=t>>2, pq=(t&3)*16;
    float bb=__ldg(bias+m0+m);
    float* op=out+(size_t)b*C_*P_+(size_t)(m0+m)*P_+p0+pq;
    #pragma unroll
    for(int j=0;j<16;j+=4){
      float4 v=*(float4*)&sC[m*68+pq+j];
      v.x+=bb;v.y+=bb;v.z+=bb;v.w+=bb;
      *(float4*)(op+j)=v;
    }
  }
}

__global__ __launch_bounds__(256) void k_h1(const float* __restrict__ lw,
    const float* __restrict__ lb,
    const float* __restrict__ p1w,const float* __restrict__ p1b){
  __shared__ float mxc[128];
  __shared__ float mx[128];
  int b=blockIdx.x,t=threadIdx.x;
  if(t<128) mxc[t]=g_meanxc[b*128+t];
  __syncthreads();
  if(t<128){
    float a=__ldg(lb+t);
    #pragma unroll 4
    for(int c=0;c<128;c++) a+=mxc[c]*__ldg(lw+t*128+c);
    mx[t]=a;
  }
  __syncthreads();
  float a=__ldg(p1b+t);
  #pragma unroll 4
  for(int c=0;c<128;c++) a+=mx[c]*__ldg(p1w+t*128+c);
  g_h1[b*256+t]=a>0.f?a:0.1f*a;
}

__global__ __launch_bounds__(256) void k_router(const float* __restrict__ p2w,
    const float* __restrict__ p2b,
    const float* __restrict__ g1,const float* __restrict__ b1,
    const float* __restrict__ g2,const float* __restrict__ b2,
    const float* __restrict__ p3w,const float* __restrict__ p3b,
    const float* __restrict__ gum){
  __shared__ float sw[8192];
  __shared__ float h2[1024];
  int t=threadIdx.x;
  for(int i=t;i<8192;i+=256) sw[i]=p2w[i];
  {
    int o=t;
    float v[32]; float s=0.f,s2=0.f;
    #pragma unroll
    for(int b=0;b<32;b++){float x=g_h1[b*256+o]; v[b]=x; s+=x; s2+=x*x;}
    float mu=s*(1.f/32.f), rs=rsqrtf(fmaxf(s2*(1.f/32.f)-mu*mu,0.f)+1e-5f);
    float gg=g1[o], bb=b1[o];
    #pragma unroll
    for(int b=0;b<32;b++) g_h1[b*256+o]=(v[b]-mu)*rs*gg+bb;
  }
  __syncthreads();
  for(int idx=t;idx<1024;idx+=256){
    int b=idx>>5, j=idx&31;
    float a=p2b[j];
    const float* hb=g_h1+b*256;
    #pragma unroll 4
    for(int o=0;o<256;o++) a+=hb[o]*sw[j*256+o];
    h2[idx]=a>0.f?a:0.1f*a;
  }
  __syncthreads();
  if(t<32){int j=t;float s=0,s2=0;
   for(int b=0;b<32;b++){float v=h2[b*32+j];s+=v;s2+=v*v;}
   float mu=s/32.f,rs=rsqrtf(fmaxf(s2/32.f-mu*mu,0.f)+1e-5f);
   for(int b=0;b<32;b++)h2[b*32+j]=(h2[b*32+j]-mu)*rs*g2[j]+b2[j];}
  __syncthreads();
  if(t<32){int b=t;float best=-1e30f;int bi=0;
   for(int r=0;r<3;r++){
     float l=p3b[r]+gum[b*3+r];
     for(int j=0;j<32;j++)l+=h2[b*32+j]*p3w[r*32+j];
     if(l>best){best=l;bi=r;}
   }
   g_expert[b]=bi;}
}

__device__ __forceinline__ void rmm4(float* sP,const float* M,int tr){
  int t=threadIdx.x; int j0=(t&15)*4, r0=(t>>4)*4;
  float acc[4][4]={};
  for(int k=0;k<64;k++){
    float xv[4];
    #pragma unroll
    for(int jj=0;jj<4;jj++) xv[jj]=sP[k*65+j0+jj];
    #pragma unroll
    for(int rr=0;rr<4;rr++){
      float m=tr?M[k*64+r0+rr]:M[(r0+rr)*64+k];
      #pragma unroll
      for(int jj=0;jj<4;jj++) acc[rr][jj]+=m*xv[jj];
    }
  }
  __syncthreads();
  #pragma unroll
  for(int rr=0;rr<4;rr++)
    #pragma unroll
    for(int jj=0;jj<4;jj++) sP[(j0+jj)*65+r0+rr]=acc[rr][jj];
  __syncthreads();
}

__global__ __launch_bounds__(256) void k_dct(){
  int c=blockIdx.x,b=blockIdx.y;
  if(g_expert[b]!=0)return;
  __shared__ float sP[64*65]; __shared__ float sM[4096];
  int t=threadIdx.x;
  const float* src=g_xl+(size_t)(b*256+c)*P_;
  for(int idx=t;idx<4096;idx+=256){sM[idx]=g_wn[idx];sP[(idx>>6)*65+(idx&63)]=src[idx];}
  __syncthreads();
  rmm4(sP,sM,0);
  rmm4(sP,sM,0);
  for(int idx=t;idx<4096;idx+=256)sP[(idx>>6)*65+(idx&63)]*=__ldg(&g_we[c*P_+idx]);
  __syncthreads();
  rmm4(sP,sM,1);
  rmm4(sP,sM,1);
  float* dst=g_xo+(size_t)(b*C_+c)*P_;
  for(int idx=t;idx<4096;idx+=256)dst[idx]=sP[(idx>>6)*65+(idx&63)];
}

__device__ __forceinline__ float2 cmul(float2 a,float2 b){return make_float2(a.x*b.x-a.y*b.y,a.x*b.y+a.y*b.x);}
__device__ __forceinline__ float2 cmulc(float2 a,float2 b){return make_float2(a.x*b.x+a.y*b.y,a.y*b.x-a.x*b.y);}
__device__ __forceinline__ float2 cadd(float2 a,float2 b){return make_float2(a.x+b.x,a.y+b.y);}
__device__ __forceinline__ float2 csub(float2 a,float2 b){return make_float2(a.x-b.x,a.y-b.y);}

__device__ __forceinline__ void fft8(float2* a,float s){
  const float c8=0.70710678118654752f;
  float2 w1=make_float2(c8,s*c8),w2=make_float2(0.f,s),w3=make_float2(-c8,s*c8),t;
  t=csub(a[0],a[4]);a[0]=cadd(a[0],a[4]);a[4]=t;
  t=csub(a[1],a[5]);a[1]=cadd(a[1],a[5]);a[5]=cmul(t,w1);
  t=csub(a[2],a[6]);a[2]=cadd(a[2],a[6]);a[6]=cmul(t,w2);
  t=csub(a[3],a[7]);a[3]=cadd(a[3],a[7]);a[7]=cmul(t,w3);
  t=csub(a[0],a[2]);a[0]=cadd(a[0],a[2]);a[2]=t;
  t=csub(a[1],a[3]);a[1]=cadd(a[1],a[3]);a[3]=cmul(t,w2);
  t=csub(a[4],a[6]);a[4]=cadd(a[4],a[6]);a[6]=t;
  t=csub(a[5],a[7]);a[5]=cadd(a[5],a[7]);a[7]=cmul(t,w2);
  t=csub(a[0],a[1]);a[0]=cadd(a[0],a[1]);a[1]=t;
  t=csub(a[2],a[3]);a[2]=cadd(a[2],a[3]);a[3]=t;
  t=csub(a[4],a[5]);a[4]=cadd(a[4],a[5]);a[5]=t;
  t=csub(a[6],a[7]);a[6]=cadd(a[6],a[7]);a[7]=t;
  t=a[1];a[1]=a[4];a[4]=t;
  t=a[3];a[3]=a[6];a[6]=t;
}

__device__ void fft64_dir(float2* sP,int es,int vs,float sgn,bool inverse){
  int t=threadIdx.x,v=t&63,sl=t>>6;
  #pragma unroll
  for(int gi=0;gi<2;gi++){
    int g=sl+gi*4;
    float2 a[8];
    if(!inverse){
      #pragma unroll
      for(int n1=0;n1<8;n1++)a[n1]=sP[(8*n1+g)*es+v*vs];
      fft8(a,sgn);
      #pragma unroll
      for(int k1=1;k1<8;k1++)a[k1]=cmul(a[k1],__ldg(&g_F64[g*64+k1]));
      #pragma unroll
      for(int k1=0;k1<8;k1++)sP[(8*k1+g)*es+v*vs]=a[k1];
    }else{
      #pragma unroll
      for(int k2=0;k2<8;k2++)a[k2]=sP[(8*g+k2)*es+v*vs];
      fft8(a,sgn);
      #pragma unroll
      for(int n2=1;n2<8;n2++)a[n2]=cmulc(a[n2],__ldg(&g_F64[n2*64+g]));
      #pragma unroll
      for(int n2=0;n2<8;n2++)sP[(8*g+n2)*es+v*vs]=a[n2];
    }
  }
  __syncthreads();
  #pragma unroll
  for(int gi=0;gi<2;gi++){
    int g=sl+gi*4;
    float2 a[8];
    if(!inverse){
      #pragma unroll
      for(int n2=0;n2<8;n2++)a[n2]=sP[(8*g+n2)*es+v*vs];
      fft8(a,sgn);
      #pragma unroll
      for(int k2=0;k2<8;k2++)sP[(8*g+k2)*es+v*vs]=a[k2];
    }else{
      #pragma unroll
      for(int k1=0;k1<8;k1++)a[k1]=sP[(8*k1+g)*es+v*vs];
      fft8(a,sgn);
      #pragma unroll
      for(int n1=0;n1<8;n1++)sP[(8*n1+g)*es+v*vs]=a[n1];
    }
  }
  __syncthreads();
}

__global__ __launch_bounds__(256) void k_pfft(){
  int ki=blockIdx.x,b=blockIdx.y;
  if(g_expert[b]!=1)return;
  bool noim=(ki==0)||(ki==64);
  __shared__ float2 sP[64*65];
  int t=threadIdx.x;
  float* re=g_cA+(size_t)(b*256+ki)*P_;
  float* im=g_cA+(size_t)(b*256+64+ki)*P_;
  for(int idx=t;idx<4096;idx+=256)
    sP[(idx>>6)*65+(idx&63)]=make_float2(re[idx],noim?0.f:im[idx]);
  __syncthreads();
  fft64_dir(sP,65,1,-1.f,false);
  fft64_dir(sP,1,65,-1.f,false);
  for(int idx=t;idx<4096;idx+=256){
    int ph=idx>>6,pw=idx&63;
    int f=(((ph&7)<<3)|(ph>>3))*64+(((pw&7)<<3)|(pw>>3));
    float w=__ldg(&g_weS[ki*P_+f])*(1.f/4096.f);
    float2 v=sP[ph*65+pw];
    sP[ph*65+pw]=make_float2(v.x*w,v.y*w);
  }
  __syncthreads();
  fft64_dir(sP,1,65,1.f,true);
  fft64_dir(sP,65,1,1.f,true);
  for(int idx=t;idx<4096;idx+=256){
    float2 v=sP[(idx>>6)*65+(idx&63)];
    re[idx]=v.x;
    if(!noim) im[idx]=v.y;
  }
}

__global__ __launch_bounds__(256) void k_haar(){
  int b=blockIdx.y;
  if(g_expert[b]!=2)return;
  int gid=blockIdx.x*256+threadIdx.x;
  int cp=gid>>11,q=gid&2047,h=q>>5,wp=q&31;
  size_t i0=(size_t)(b*256+2*cp)*P_+h*64+2*wp;
  float2 t0=*(const float2*)(g_xl+i0);
  float2 t1=*(const float2*)(g_xl+i0+P_);
  float sab=t0.x+t0.y,dab=t0.x-t0.y,scd=t1.x+t1.y,dcd=t1.x-t1.y;
  int pa=h*64+wp,pd=h*64+32+wp;
  float u00=(sab+scd)*0.25f*__ldg(&g_we[cp*P_+pa]);
  float u10=(sab-scd)*0.25f*__ldg(&g_we[(64+cp)*P_+pa]);
  float u01=(dab+dcd)*0.25f*__ldg(&g_we[cp*P_+pd]);
  float u11=(dab-dcd)*0.25f*__ldg(&g_we[(64+cp)*P_+pd]);
  float r0=u00+u01,r1=u00-u01,s0=u10+u11,s1=u10-u11;
  size_t o0=(size_t)(b*C_+2*cp)*P_+h*64+2*wp;
  *(float2*)(g_xo+o0)=make_float2(r0+s0,r1+s1);
  *(float2*)(g_xo+o0+P_)=make_float2(r0-s0,r1-s1);
}

extern "C" void kernel_launch(void* const* d_in,const int* in_sizes,int n_in,
                              void* d_out,int out_size){
  const float* x=(const float*)d_in[0];
  const float* fe=(const float*)d_in[1];
  const float* dww=(const float*)d_in[2];
  const float* dwb=(const float*)d_in[3];
  const float* lw=(const float*)d_in[4];
  const float* lb=(const float*)d_in[5];
  const float* p1w=(const float*)d_in[6];
  const float* p1b=(const float*)d_in[7];
  const float* g1=(const float*)d_in[8];
  const float* b1=(const float*)d_in[9];
  const float* p2w=(const float*)d_in[10];
  const float* p2b=(const float*)d_in[11];
  const float* g2=(const float*)d_in[12];
  const float* b2=(const float*)d_in[13];
  const float* p3w=(const float*)d_in[14];
  const float* p3b=(const float*)d_in[15];
  const float* tw=(const float*)d_in[16];
  const float* tb=(const float*)d_in[17];
  const float* og=(const float*)d_in[18];
  const float* ob=(const float*)d_in[19];
  const float* olw=(const float*)d_in[20];
  const float* olb=(const float*)d_in[21];
  const float* gum=(const float*)d_in[22];
  float* out=(float*)d_out;
  float *gxc,*gxl,*gca,*gwcf2,*gbff,*gwci,*gxo;
  cudaGetSymbolAddress((void**)&gxc,g_xc);
  cudaGetSymbolAddress((void**)&gxl,g_xl);
  cudaGetSymbolAddress((void**)&gxo,g_xo);
  cudaGetSymbolAddress((void**)&gca,g_cA);
  cudaGetSymbolAddress((void**)&gwcf2,g_WCf2);
  cudaGetSymbolAddress((void**)&gbff,g_bFf);
  cudaGetSymbolAddress((void**)&gwci,g_WCi);

  static cudaStream_t s1=0,s2=0;
  static cudaEvent_t ev0=0,evA=0,evConv=0,evR=0,evG1=0,evC=0,evS2=0;
  if(!s1){
    cudaStreamCreateWithFlags(&s1,cudaStreamNonBlocking);
    cudaStreamCreateWithFlags(&s2,cudaStreamNonBlocking);
    cudaEventCreateWithFlags(&ev0,cudaEventDisableTiming);
    cudaEventCreateWithFlags(&evA,cudaEventDisableTiming);
    cudaEventCreateWithFlags(&evConv,cudaEventDisableTiming);
    cudaEventCreateWithFlags(&evR,cudaEventDisableTiming);
    cudaEventCreateWithFlags(&evG1,cudaEventDisableTiming);
    cudaEventCreateWithFlags(&evC,cudaEventDisableTiming);
    cudaEventCreateWithFlags(&evS2,cudaEventDisableTiming);
  }

  // fork
  cudaEventRecord(ev0,0);
  cudaStreamWaitEvent(s1,ev0,0);
  cudaStreamWaitEvent(s2,ev0,0);

  // s1: constants, filter, folded FFT-forward weights
  k_consts<<<64,256,0,s1>>>();
  k_we<<<128,256,0,s1>>>(fe,tw,tb);
  k_weS<<<65,256,0,s1>>>();
  k_combine<<<128,128,0,s1>>>(lw,lb);
  cudaEventRecord(evA,s1);

  // main: conv (fused mean)
  k_conv<<<dim3(128,32),256>>>(x,dww,dwb);
  cudaEventRecord(evConv,0);

  // s2: router chain
  cudaStreamWaitEvent(s2,evConv,0);
  k_h1<<<32,256,0,s2>>>(lw,lb,p1w,p1b);
  k_router<<<1,256,0,s2>>>(p2w,p2b,g1,b1,g2,b2,p3w,p3b,gum);
  cudaEventRecord(evR,s2);

  // main: gemm1 z-half (all batches), then gated x-half (non-FFT batches)
  k_gemm<<<dim3(64,2,32),256>>>(gxc,(size_t)128*P_,128,lw+128*128,lb+128,gxl+128*P_,(size_t)256*P_,-1);
  cudaStreamWaitEvent(0,evR,0);
  k_gemm<<<dim3(64,2,32),256>>>(gxc,(size_t)128*P_,128,lw,lb,gxl,(size_t)256*P_,-2);
  cudaEventRecord(evG1,0);

  // s2: FFT expert chain from conv output (folded weights)
  cudaStreamWaitEvent(s2,evA,0);
  k_gemm<<<dim3(64,2,32),256,0,s2>>>(gxc,(size_t)128*P_,128,gwcf2,gbff,gca,(size_t)256*P_,1);
  k_pfft<<<dim3(65,32),256,0,s2>>>();
  k_gemm<<<dim3(64,2,32),256,0,s2>>>(gca,(size_t)256*P_,128,gwci,(const float*)0,gxo,(size_t)128*P_,1);
  cudaStreamWaitEvent(s2,evG1,0);   // z needed by lngemm
  k_lngemm<<<dim3(64,2,32),256,0,s2>>>(olw,olb,og,ob,out,1);
  cudaEventRecord(evS2,s2);

  // main: Haar expert chain
  cudaStreamWaitEvent(0,evA,0);
  k_haar<<<dim3(512,32),256>>>();
  k_lngemm<<<dim3(64,2,32),256>>>(olw,olb,og,ob,out,2);

  // s1: DCT expert chain
  cudaStreamWaitEvent(s1,evG1,0);
  cudaStreamWaitEvent(s1,evR,0);
  k_dct<<<dim3(128,32),256,0,s1>>>();
  k_lngemm<<<dim3(64,2,32),256,0,s1>>>(olw,olb,og,ob,out,0);
  cudaEventRecord(evC,s1);

  // join
  cudaStreamWaitEvent(0,evC,0);
  cudaStreamWaitEvent(0,evS2,0);
}

// round 17
// speedup vs baseline: 1.1912x; 1.1912x over previous
#include <cuda_runtime.h>
#include <mma.h>
#include <cstdint>
using namespace nvcuda;
#define B_ 32
#define C_ 128
#define P_ 4096
#define PI_ 3.14159265358979323846f

__device__ float  g_xc[B_*C_*P_];
__device__ float  g_xl[B_*256*P_];
__device__ float  g_xo[B_*C_*P_];
__device__ float  g_cA[B_*256*P_];
__device__ float  g_we[C_*P_];
__device__ float  g_weS[65*P_];
__device__ float  g_wn[4096];
__device__ float2 g_F64[4096];
__device__ float  g_WCf[128*128];
__device__ float  g_WCi[128*128];
__device__ float  g_WCf2[128*128];
__device__ float  g_bFf[128];
__device__ float  g_meanxc[B_*C_];
__device__ float  g_h1[B_*256];
__device__ int    g_expert[B_];

__device__ __forceinline__ float t32(float v){return wmma::__float_to_tf32(v);}

__global__ void k_consts(){
  int i=blockIdx.x*256+threadIdx.x;
  if(i<4096){
    int n=i>>6,h=i&63;
    float v=cospif((float)n*(h+0.5f)/64.f)*sqrtf(2.f/64.f);
    if(n==0)v*=0.70710678118654752f;
    g_wn[i]=v;
    float a=(float)((n*h)&63)/32.f;
    g_F64[i]=make_float2(cospif(a),-sinpif(a));
  }
  if(i<16384){
    int r=i>>7, j=i&127;
    if(r<=64){
      g_WCf[i]=cospif((float)((r*j)&127)/64.f);
    }else{
      int k=r-64;
      g_WCf[i]=-sinpif((float)((k*j)&127)/64.f);
    }
    int c=r;
    if(j<=64){
      float s=(j==0||j==64)?1.f:2.f;
      g_WCi[c*128+j]=s*cospif((float)((j*c)&127)/64.f)*(1.f/128.f);
    }else{
      int k=j-64;
      g_WCi[c*128+j]=-2.f*sinpif((float)((k*c)&127)/64.f)*(1.f/128.f);
    }
  }
}

__global__ __launch_bounds__(128) void k_combine(const float* __restrict__ lw,
    const float* __restrict__ lb){
  __shared__ float srow[128];
  int r=blockIdx.x, t=threadIdx.x;
  srow[t]=g_WCf[r*128+t];
  __syncthreads();
  float a=0.f;
  #pragma unroll 4
  for(int j=0;j<128;j++) a+=srow[j]*__ldg(lw+j*128+t);
  g_WCf2[r*128+t]=a;
  if(t==0){
    float bsum=0.f;
    for(int j=0;j<128;j++) bsum+=srow[j]*__ldg(lb+j);
    g_bFf[r]=bsum;
  }
}

__global__ __launch_bounds__(256) void k_we(const float* __restrict__ fe,
    const float* __restrict__ tw,const float* __restrict__ tb){
  __shared__ float sfe[128*33];
  __shared__ float stw[128*32];
  int t=threadIdx.x,p0=blockIdx.x*32;
  for(int idx=t;idx<4096;idx+=256){int pl=idx>>7,c=idx&127;sfe[c*33+pl]=fe[(p0+pl)*128+c];}
  int pl=t&31,cg=t>>5;
  int p=p0+pl,h=p>>6,w=p&63;
  float s=(PI_*PI_/4096.f)*(float)(h*h+w*w);
  float acc[16];
  #pragma unroll
  for(int i=0;i<16;i++)acc[i]=0.f;
  for(int ct=0;ct<4;ct++){
    __syncthreads();
    for(int idx=t;idx<4096;idx+=256){
      int o=idx>>5, cc=idx&31;
      stw[o*32+cc]=tw[o*128+ct*32+cc];
    }
    __syncthreads();
    #pragma unroll
    for(int cc=0;cc<32;cc++){
      float f=sfe[(ct*32+cc)*33+pl];
      #pragma unroll
      for(int i=0;i<16;i++)acc[i]+=f*stw[(cg*16+i)*32+cc];
    }
  }
  #pragma unroll
  for(int i=0;i<16;i++){
    int c=cg*16+i;
    float k=fmaxf(acc[i]+__ldg(tb+c),0.f);
    g_we[c*P_+p]=expf(-s*k);
  }
}

__global__ void k_weS(){
  int ki=blockIdx.x;
  for(int p=threadIdx.x;p<4096;p+=256){
    int fh=p>>6, fw=p&63;
    int kn=(128-ki)&127, hn=(64-fh)&63, wn=(64-fw)&63;
    g_weS[ki*P_+p]=0.5f*(g_we[ki*P_+p]+g_we[kn*P_+hn*64+wn]);
  }
}

__global__ __launch_bounds__(256) void k_conv(const float* __restrict__ x,
    const float* __restrict__ wt,const float* __restrict__ bs){
  int c=blockIdx.x,b=blockIdx.y;
  __shared__ float sT[66*72];
  __shared__ float red[256];
  int t=threadIdx.x;
  const float* xp=x+(size_t)(b*C_+c)*P_;
  for(int i=t;i<66*72;i+=256) sT[i]=0.f;
  __syncthreads();
  #pragma unroll
  for(int i=0;i<4;i++){
    int vidx=t+i*256;
    int r=vidx>>4, cq=vidx&15;
    float4 v=*(const float4*)(xp+r*64+cq*4);
    *(float4*)&sT[(r+1)*72+4+cq*4]=v;
  }
  __syncthreads();
  const float* wc=wt+c*9;
  float w0=__ldg(wc+0),w1=__ldg(wc+1),w2=__ldg(wc+2),
        w3=__ldg(wc+3),w4=__ldg(wc+4),w5=__ldg(wc+5),
        w6=__ldg(wc+6),w7=__ldg(wc+7),w8=__ldg(wc+8);
  float bb=__ldg(bs+c);
  float tot=0.f;
  float* op=g_xc+(size_t)(b*C_+c)*P_;
  #pragma unroll
  for(int i=0;i<16;i++){
    int p=t+i*256; int r=p>>6, cl=p&63;
    const float* s=&sT[r*72+cl+3];
    float acc=bb + w0*s[0]+w1*s[1]+w2*s[2]
                 + w3*s[72]+w4*s[73]+w5*s[74]
                 + w6*s[144]+w7*s[145]+w8*s[146];
    op[p]=acc; tot+=acc;
  }
  red[t]=tot; __syncthreads();
  for(int st=128;st>0;st>>=1){if(t<st)red[t]+=red[t+st];__syncthreads();}
  if(t==0) g_meanxc[b*128+c]=red[0]*(1.f/4096.f);
}

// TF32 tensor gemm (R15 single-buffered mainloop), bias folded into accumulator
// init, direct fragment store to global. K must be multiple of 32.
// gate>=0: expert==gate; gate==-1: all; gate==-2: expert!=1.
__global__ __launch_bounds__(256) void k_gemm(const float* __restrict__ in, size_t inBS, int K,
    const float* __restrict__ W,const float* __restrict__ bias,
    float* __restrict__ out, size_t outBS, int gate){
  int b=blockIdx.z;
  if(gate>=0 && g_expert[b]!=gate)return;
  if(gate==-2 && g_expert[b]==1)return;
  __shared__ __align__(32) float sA[64*36];
  __shared__ __align__(32) float sB[32*68];
  __shared__ float sBias[64*16];
  int t=threadIdx.x, m0=blockIdx.y*64, p0=blockIdx.x*64;
  int warp=t>>5, mt=warp&3, nh=warp>>2;
  const float* X=in+(size_t)b*inBS;

  // bias tile: row m (0..63) replicated across 16 cols
  #pragma unroll
  for(int i=0;i<4;i++){
    int idx=t+i*256; int m=idx>>4;
    sBias[idx]=bias?__ldg(bias+m0+m):0.f;
  }
  __syncthreads();

  wmma::fragment<wmma::accumulator,16,16,8,float> c0,c1;
  wmma::load_matrix_sync(c0,&sBias[mt*16*16],16,wmma::mem_row_major);
  c1=c0;
  wmma::fragment<wmma::matrix_a,16,16,8,wmma::precision::tf32,wmma::row_major> af;
  wmma::fragment<wmma::matrix_b,16,16,8,wmma::precision::tf32,wmma::row_major> b0,b1;

  for(int k0=0;k0<K;k0+=32){
    {
      int m=t>>2, kq=(t&3)*8;
      const float* wp=W+(size_t)(m0+m)*K+k0+kq;
      float4 v0=*(const float4*)wp, v1=*(const float4*)(wp+4);
      float* d=&sA[m*36+kq];
      d[0]=t32(v0.x); d[1]=t32(v0.y); d[2]=t32(v0.z); d[3]=t32(v0.w);
      d[4]=t32(v1.x); d[5]=t32(v1.y); d[6]=t32(v1.z); d[7]=t32(v1.w);
    }
    {
      int k=t>>3, pq=(t&7)*8;
      const float* xp=X+(size_t)(k0+k)*P_+p0+pq;
      float4 v0=*(const float4*)xp, v1=*(const float4*)(xp+4);
      float* d=&sB[k*68+pq];
      d[0]=t32(v0.x); d[1]=t32(v0.y); d[2]=t32(v0.z); d[3]=t32(v0.w);
      d[4]=t32(v1.x); d[5]=t32(v1.y); d[6]=t32(v1.z); d[7]=t32(v1.w);
    }
    __syncthreads();
    #pragma unroll
    for(int kk=0;kk<4;kk++){
      wmma::load_matrix_sync(af,&sA[mt*16*36+kk*8],36);
      wmma::load_matrix_sync(b0,&sB[kk*8*68+nh*32],68);
      wmma::load_matrix_sync(b1,&sB[kk*8*68+nh*32+16],68);
      wmma::mma_sync(c0,af,b0,c0);
      wmma::mma_sync(c1,af,b1,c1);
    }
    __syncthreads();
  }
  float* op=out+(size_t)b*outBS+(size_t)(m0+mt*16)*P_+p0+nh*32;
  wmma::store_matrix_sync(op,c0,P_,wmma::mem_row_major);
  wmma::store_matrix_sync(op+16,c1,P_,wmma::mem_row_major);
}

// fused LN + silu-gate + final gemm (SIMT fp32, R15 version)
__global__ __launch_bounds__(256) void k_lngemm(
    const float* __restrict__ W,const float* __restrict__ bias,
    const float* __restrict__ og,const float* __restrict__ ob,
    float* __restrict__ out,int gate){
  int b=blockIdx.z;
  if(g_expert[b]!=gate)return;
  __shared__ float sA[16*68]; __shared__ float4 sB[256];
  __shared__ float part[256],part2[256];
  __shared__ float smu[64],srs[64];
  int m0=blockIdx.y*64,p0=blockIdx.x*64,t=threadIdx.x;
  int tx=t&15,ty=t>>4;
  {
    int p=t&63,q=t>>6;
    float s=0.f,s2=0.f;
    for(int c=q*32;c<q*32+32;c++){
      float v=g_xo[(size_t)(b*C_+c)*P_+p0+p];
      s+=v;s2+=v*v;
    }
    part[t]=s;part2[t]=s2;
  }
  __syncthreads();
  if(t<64){
    float S=part[t]+part[t+64]+part[t+128]+part[t+192];
    float S2=part2[t]+part2[t+64]+part2[t+128]+part2[t+192];
    float m=S*(1.f/128.f);
    smu[t]=m;
    srs[t]=rsqrtf(fmaxf(S2*(1.f/128.f)-m*m,0.f)+1e-5f);
  }
  __syncthreads();
  float acc[4][4]={};
  for(int kt=0;kt<8;kt++){
    #pragma unroll
    for(int i=0;i<4;i++){int idx=t+i*256;sA[(idx&15)*68+(idx>>4)]=W[(size_t)(m0+(idx>>4))*128+kt*16+(idx&15)];}
    {
      int k=t>>4, px=tx*4;
      int c=kt*16+k;
      float4 xo4=*(const float4*)(g_xo+(size_t)(b*C_+c)*P_+p0+px);
      float4 z4 =*(const float4*)(g_xl+(size_t)(b*256+128+c)*P_+p0+px);
      float gg=__ldg(og+c), bo=__ldg(ob+c);
      float4 y;
      y.x=((xo4.x-smu[px+0])*srs[px+0]*gg+bo)*(z4.x/(1.f+expf(-z4.x)));
      y.y=((xo4.y-smu[px+1])*srs[px+1]*gg+bo)*(z4.y/(1.f+expf(-z4.y)));
      y.z=((xo4.z-smu[px+2])*srs[px+2]*gg+bo)*(z4.z/(1.f+expf(-z4.z)));
      y.w=((xo4.w-smu[px+3])*srs[px+3]*gg+bo)*(z4.w/(1.f+expf(-z4.w)));
      sB[k*16+tx]=y;
    }
    __syncthreads();
    #pragma unroll
    for(int k=0;k<16;k++){
      float4 bv=sB[k*16+tx];
      float4 av=*(const float4*)&sA[k*68+ty*4];
      acc[0][0]+=av.x*bv.x;acc[0][1]+=av.x*bv.y;acc[0][2]+=av.x*bv.z;acc[0][3]+=av.x*bv.w;
      acc[1][0]+=av.y*bv.x;acc[1][1]+=av.y*bv.y;acc[1][2]+=av.y*bv.z;acc[1][3]+=av.y*bv.w;
      acc[2][0]+=av.z*bv.x;acc[2][1]+=av.z*bv.y;acc[2][2]+=av.z*bv.z;acc[2][3]+=av.z*bv.w;
      acc[3][0]+=av.w*bv.x;acc[3][1]+=av.w*bv.y;acc[3][2]+=av.w*bv.z;acc[3][3]+=av.w*bv.w;
    }
    __syncthreads();
  }
  #pragma unroll
  for(int i=0;i<4;i++){
    int m=m0+ty*4+i;
    float bb=__ldg(bias+m);
    *(float4*)(out+(size_t)b*C_*P_+(size_t)m*P_+p0+tx*4)=
      make_float4(acc[i][0]+bb,acc[i][1]+bb,acc[i][2]+bb,acc[i][3]+bb);
  }
}

__global__ __launch_bounds__(256) void k_h1(const float* __restrict__ lw,
    const float* __restrict__ lb,
    const float* __restrict__ p1w,const float* __restrict__ p1b){
  __shared__ float mxc[128];
  __shared__ float mx[128];
  int b=blockIdx.x,t=threadIdx.x;
  if(t<128) mxc[t]=g_meanxc[b*128+t];
  __syncthreads();
  if(t<128){
    float a=__ldg(lb+t);
    #pragma unroll 4
    for(int c=0;c<128;c++) a+=mxc[c]*__ldg(lw+t*128+c);
    mx[t]=a;
  }
  __syncthreads();
  float a=__ldg(p1b+t);
  #pragma unroll 4
  for(int c=0;c<128;c++) a+=mx[c]*__ldg(p1w+t*128+c);
  g_h1[b*256+t]=a>0.f?a:0.1f*a;
}

__global__ __launch_bounds__(256) void k_router(const float* __restrict__ p2w,
    const float* __restrict__ p2b,
    const float* __restrict__ g1,const float* __restrict__ b1,
    const float* __restrict__ g2,const float* __restrict__ b2,
    const float* __restrict__ p3w,const float* __restrict__ p3b,
    const float* __restrict__ gum){
  __shared__ float sw[8192];
  __shared__ float h2[1024];
  int t=threadIdx.x;
  for(int i=t;i<8192;i+=256) sw[i]=p2w[i];
  {
    int o=t;
    float v[32]; float s=0.f,s2=0.f;
    #pragma unroll
    for(int b=0;b<32;b++){float x=g_h1[b*256+o]; v[b]=x; s+=x; s2+=x*x;}
    float mu=s*(1.f/32.f), rs=rsqrtf(fmaxf(s2*(1.f/32.f)-mu*mu,0.f)+1e-5f);
    float gg=g1[o], bb=b1[o];
    #pragma unroll
    for(int b=0;b<32;b++) g_h1[b*256+o]=(v[b]-mu)*rs*gg+bb;
  }
  __syncthreads();
  for(int idx=t;idx<1024;idx+=256){
    int b=idx>>5, j=idx&31;
    float a=p2b[j];
    const float* hb=g_h1+b*256;
    #pragma unroll 4
    for(int o=0;o<256;o++) a+=hb[o]*sw[j*256+o];
    h2[idx]=a>0.f?a:0.1f*a;
  }
  __syncthreads();
  if(t<32){int j=t;float s=0,s2=0;
   for(int b=0;b<32;b++){float v=h2[b*32+j];s+=v;s2+=v*v;}
   float mu=s/32.f,rs=rsqrtf(fmaxf(s2/32.f-mu*mu,0.f)+1e-5f);
   for(int b=0;b<32;b++)h2[b*32+j]=(h2[b*32+j]-mu)*rs*g2[j]+b2[j];}
  __syncthreads();
  if(t<32){int b=t;float best=-1e30f;int bi=0;
   for(int r=0;r<3;r++){
     float l=p3b[r]+gum[b*3+r];
     for(int j=0;j<32;j++)l+=h2[b*32+j]*p3w[r*32+j];
     if(l>best){best=l;bi=r;}
   }
   g_expert[b]=bi;}
}

__device__ __forceinline__ void rmm4(float* sP,const float* M,int tr){
  int t=threadIdx.x; int j0=(t&15)*4, r0=(t>>4)*4;
  float acc[4][4]={};
  for(int k=0;k<64;k++){
    float xv[4];
    #pragma unroll
    for(int jj=0;jj<4;jj++) xv[jj]=sP[k*65+j0+jj];
    #pragma unroll
    for(int rr=0;rr<4;rr++){
      float m=tr?M[k*64+r0+rr]:M[(r0+rr)*64+k];
      #pragma unroll
      for(int jj=0;jj<4;jj++) acc[rr][jj]+=m*xv[jj];
    }
  }
  __syncthreads();
  #pragma unroll
  for(int rr=0;rr<4;rr++)
    #pragma unroll
    for(int jj=0;jj<4;jj++) sP[(j0+jj)*65+r0+rr]=acc[rr][jj];
  __syncthreads();
}

__global__ __launch_bounds__(256) void k_dct(){
  int c=blockIdx.x,b=blockIdx.y;
  if(g_expert[b]!=0)return;
  __shared__ float sP[64*65]; __shared__ float sM[4096];
  int t=threadIdx.x;
  const float* src=g_xl+(size_t)(b*256+c)*P_;
  for(int idx=t;idx<4096;idx+=256){sM[idx]=g_wn[idx];sP[(idx>>6)*65+(idx&63)]=src[idx];}
  __syncthreads();
  rmm4(sP,sM,0);
  rmm4(sP,sM,0);
  for(int idx=t;idx<4096;idx+=256)sP[(idx>>6)*65+(idx&63)]*=__ldg(&g_we[c*P_+idx]);
  __syncthreads();
  rmm4(sP,sM,1);
  rmm4(sP,sM,1);
  float* dst=g_xo+(size_t)(b*C_+c)*P_;
  for(int idx=t;idx<4096;idx+=256)dst[idx]=sP[(idx>>6)*65+(idx&63)];
}

__device__ __forceinline__ float2 cmul(float2 a,float2 b){return make_float2(a.x*b.x-a.y*b.y,a.x*b.y+a.y*b.x);}
__device__ __forceinline__ float2 cmulc(float2 a,float2 b){return make_float2(a.x*b.x+a.y*b.y,a.y*b.x-a.x*b.y);}
__device__ __forceinline__ float2 cadd(float2 a,float2 b){return make_float2(a.x+b.x,a.y+b.y);}
__device__ __forceinline__ float2 csub(float2 a,float2 b){return make_float2(a.x-b.x,a.y-b.y);}

__device__ __forceinline__ void fft8(float2* a,float s){
  const float c8=0.70710678118654752f;
  float2 w1=make_float2(c8,s*c8),w2=make_float2(0.f,s),w3=make_float2(-c8,s*c8),t;
  t=csub(a[0],a[4]);a[0]=cadd(a[0],a[4]);a[4]=t;
  t=csub(a[1],a[5]);a[1]=cadd(a[1],a[5]);a[5]=cmul(t,w1);
  t=csub(a[2],a[6]);a[2]=cadd(a[2],a[6]);a[6]=cmul(t,w2);
  t=csub(a[3],a[7]);a[3]=cadd(a[3],a[7]);a[7]=cmul(t,w3);
  t=csub(a[0],a[2]);a[0]=cadd(a[0],a[2]);a[2]=t;
  t=csub(a[1],a[3]);a[1]=cadd(a[1],a[3]);a[3]=cmul(t,w2);
  t=csub(a[4],a[6]);a[4]=cadd(a[4],a[6]);a[6]=t;
  t=csub(a[5],a[7]);a[5]=cadd(a[5],a[7]);a[7]=cmul(t,w2);
  t=csub(a[0],a[1]);a[0]=cadd(a[0],a[1]);a[1]=t;
  t=csub(a[2],a[3]);a[2]=cadd(a[2],a[3]);a[3]=t;
  t=csub(a[4],a[5]);a[4]=cadd(a[4],a[5]);a[5]=t;
  t=csub(a[6],a[7]);a[6]=cadd(a[6],a[7]);a[7]=t;
  t=a[1];a[1]=a[4];a[4]=t;
  t=a[3];a[3]=a[6];a[6]=t;
}

__device__ void fft64_dir(float2* sP,int es,int vs,float sgn,bool inverse){
  int t=threadIdx.x,v=t&63,sl=t>>6;
  #pragma unroll
  for(int gi=0;gi<2;gi++){
    int g=sl+gi*4;
    float2 a[8];
    if(!inverse){
      #pragma unroll
      for(int n1=0;n1<8;n1++)a[n1]=sP[(8*n1+g)*es+v*vs];
      fft8(a,sgn);
      #pragma unroll
      for(int k1=1;k1<8;k1++)a[k1]=cmul(a[k1],__ldg(&g_F64[g*64+k1]));
      #pragma unroll
      for(int k1=0;k1<8;k1++)sP[(8*k1+g)*es+v*vs]=a[k1];
    }else{
      #pragma unroll
      for(int k2=0;k2<8;k2++)a[k2]=sP[(8*g+k2)*es+v*vs];
      fft8(a,sgn);
      #pragma unroll
      for(int n2=1;n2<8;n2++)a[n2]=cmulc(a[n2],__ldg(&g_F64[n2*64+g]));
      #pragma unroll
      for(int n2=0;n2<8;n2++)sP[(8*g+n2)*es+v*vs]=a[n2];
    }
  }
  __syncthreads();
  #pragma unroll
  for(int gi=0;gi<2;gi++){
    int g=sl+gi*4;
    float2 a[8];
    if(!inverse){
      #pragma unroll
      for(int n2=0;n2<8;n2++)a[n2]=sP[(8*g+n2)*es+v*vs];
      fft8(a,sgn);
      #pragma unroll
      for(int k2=0;k2<8;k2++)sP[(8*g+k2)*es+v*vs]=a[k2];
    }else{
      #pragma unroll
      for(int k1=0;k1<8;k1++)a[k1]=sP[(8*k1+g)*es+v*vs];
      fft8(a,sgn);
      #pragma unroll
      for(int n1=0;n1<8;n1++)sP[(8*n1+g)*es+v*vs]=a[n1];
    }
  }
  __syncthreads();
}

__global__ __launch_bounds__(256) void k_pfft(){
  int ki=blockIdx.x,b=blockIdx.y;
  if(g_expert[b]!=1)return;
  bool noim=(ki==0)||(ki==64);
  __shared__ float2 sP[64*65];
  int t=threadIdx.x;
  float* re=g_cA+(size_t)(b*256+ki)*P_;
  float* im=g_cA+(size_t)(b*256+64+ki)*P_;
  for(int idx=t;idx<4096;idx+=256)
    sP[(idx>>6)*65+(idx&63)]=make_float2(re[idx],noim?0.f:im[idx]);
  __syncthreads();
  fft64_dir(sP,65,1,-1.f,false);
  fft64_dir(sP,1,65,-1.f,false);
  for(int idx=t;idx<4096;idx+=256){
    int ph=idx>>6,pw=idx&63;
    int f=(((ph&7)<<3)|(ph>>3))*64+(((pw&7)<<3)|(pw>>3));
    float w=__ldg(&g_weS[ki*P_+f])*(1.f/4096.f);
    float2 v=sP[ph*65+pw];
    sP[ph*65+pw]=make_float2(v.x*w,v.y*w);
  }
  __syncthreads();
  fft64_dir(sP,1,65,1.f,true);
  fft64_dir(sP,65,1,1.f,true);
  for(int idx=t;idx<4096;idx+=256){
    float2 v=sP[(idx>>6)*65+(idx&63)];
    re[idx]=v.x;
    if(!noim) im[idx]=v.y;
  }
}

__global__ __launch_bounds__(256) void k_haar(){
  int b=blockIdx.y;
  if(g_expert[b]!=2)return;
  int gid=blockIdx.x*256+threadIdx.x;
  int cp=gid>>11,q=gid&2047,h=q>>5,wp=q&31;
  size_t i0=(size_t)(b*256+2*cp)*P_+h*64+2*wp;
  float2 t0=*(const float2*)(g_xl+i0);
  float2 t1=*(const float2*)(g_xl+i0+P_);
  float sab=t0.x+t0.y,dab=t0.x-t0.y,scd=t1.x+t1.y,dcd=t1.x-t1.y;
  int pa=h*64+wp,pd=h*64+32+wp;
  float u00=(sab+scd)*0.25f*__ldg(&g_we[cp*P_+pa]);
  float u10=(sab-scd)*0.25f*__ldg(&g_we[(64+cp)*P_+pa]);
  float u01=(dab+dcd)*0.25f*__ldg(&g_we[cp*P_+pd]);
  float u11=(dab-dcd)*0.25f*__ldg(&g_we[(64+cp)*P_+pd]);
  float r0=u00+u01,r1=u00-u01,s0=u10+u11,s1=u10-u11;
  size_t o0=(size_t)(b*C_+2*cp)*P_+h*64+2*wp;
  *(float2*)(g_xo+o0)=make_float2(r0+s0,r1+s1);
  *(float2*)(g_xo+o0+P_)=make_float2(r0-s0,r1-s1);
}

extern "C" void kernel_launch(void* const* d_in,const int* in_sizes,int n_in,
                              void* d_out,int out_size){
  const float* x=(const float*)d_in[0];
  const float* fe=(const float*)d_in[1];
  const float* dww=(const float*)d_in[2];
  const float* dwb=(const float*)d_in[3];
  const float* lw=(const float*)d_in[4];
  const float* lb=(const float*)d_in[5];
  const float* p1w=(const float*)d_in[6];
  const float* p1b=(const float*)d_in[7];
  const float* g1=(const float*)d_in[8];
  const float* b1=(const float*)d_in[9];
  const float* p2w=(const float*)d_in[10];
  const float* p2b=(const float*)d_in[11];
  const float* g2=(const float*)d_in[12];
  const float* b2=(const float*)d_in[13];
  const float* p3w=(const float*)d_in[14];
  const float* p3b=(const float*)d_in[15];
  const float* tw=(const float*)d_in[16];
  const float* tb=(const float*)d_in[17];
  const float* og=(const float*)d_in[18];
  const float* ob=(const float*)d_in[19];
  const float* olw=(const float*)d_in[20];
  const float* olb=(const float*)d_in[21];
  const float* gum=(const float*)d_in[22];
  float* out=(float*)d_out;
  float *gxc,*gxl,*gca,*gwcf2,*gbff,*gwci,*gxo;
  cudaGetSymbolAddress((void**)&gxc,g_xc);
  cudaGetSymbolAddress((void**)&gxl,g_xl);
  cudaGetSymbolAddress((void**)&gxo,g_xo);
  cudaGetSymbolAddress((void**)&gca,g_cA);
  cudaGetSymbolAddress((void**)&gwcf2,g_WCf2);
  cudaGetSymbolAddress((void**)&gbff,g_bFf);
  cudaGetSymbolAddress((void**)&gwci,g_WCi);

  static cudaStream_t s1=0,s2=0;
  static cudaEvent_t ev0=0,evA=0,evConv=0,evR=0,evG1=0,evC=0,evS2=0;
  if(!s1){
    cudaStreamCreateWithFlags(&s1,cudaStreamNonBlocking);
    cudaStreamCreateWithFlags(&s2,cudaStreamNonBlocking);
    cudaEventCreateWithFlags(&ev0,cudaEventDisableTiming);
    cudaEventCreateWithFlags(&evA,cudaEventDisableTiming);
    cudaEventCreateWithFlags(&evConv,cudaEventDisableTiming);
    cudaEventCreateWithFlags(&evR,cudaEventDisableTiming);
    cudaEventCreateWithFlags(&evG1,cudaEventDisableTiming);
    cudaEventCreateWithFlags(&evC,cudaEventDisableTiming);
    cudaEventCreateWithFlags(&evS2,cudaEventDisableTiming);
  }

  // fork
  cudaEventRecord(ev0,0);
  cudaStreamWaitEvent(s1,ev0,0);
  cudaStreamWaitEvent(s2,ev0,0);

  // s1: constants, filter, folded FFT-forward weights
  k_consts<<<64,256,0,s1>>>();
  k_we<<<128,256,0,s1>>>(fe,tw,tb);
  k_weS<<<65,256,0,s1>>>();
  k_combine<<<128,128,0,s1>>>(lw,lb);
  cudaEventRecord(evA,s1);

  // main: conv (fused mean)
  k_conv<<<dim3(128,32),256>>>(x,dww,dwb);
  cudaEventRecord(evConv,0);

  // s2: router chain
  cudaStreamWaitEvent(s2,evConv,0);
  k_h1<<<32,256,0,s2>>>(lw,lb,p1w,p1b);
  k_router<<<1,256,0,s2>>>(p2w,p2b,g1,b1,g2,b2,p3w,p3b,gum);
  cudaEventRecord(evR,s2);

  // main: gemm1 z-half (all batches), then gated x-half (non-FFT batches)
  k_gemm<<<dim3(64,2,32),256>>>(gxc,(size_t)128*P_,128,lw+128*128,lb+128,gxl+128*P_,(size_t)256*P_,-1);
  cudaStreamWaitEvent(0,evR,0);
  k_gemm<<<dim3(64,2,32),256>>>(gxc,(size_t)128*P_,128,lw,lb,gxl,(size_t)256*P_,-2);
  cudaEventRecord(evG1,0);

  // s2: FFT expert chain from conv output (folded weights)
  cudaStreamWaitEvent(s2,evA,0);
  k_gemm<<<dim3(64,2,32),256,0,s2>>>(gxc,(size_t)128*P_,128,gwcf2,gbff,gca,(size_t)256*P_,1);
  k_pfft<<<dim3(65,32),256,0,s2>>>();
  k_gemm<<<dim3(64,2,32),256,0,s2>>>(gca,(size_t)256*P_,128,gwci,(const float*)0,gxo,(size_t)128*P_,1);
  cudaStreamWaitEvent(s2,evG1,0);   // z needed by lngemm
  k_lngemm<<<dim3(64,2,32),256,0,s2>>>(olw,olb,og,ob,out,1);
  cudaEventRecord(evS2,s2);

  // main: Haar expert chain
  cudaStreamWaitEvent(0,evA,0);
  k_haar<<<dim3(512,32),256>>>();
  k_lngemm<<<dim3(64,2,32),256>>>(olw,olb,og,ob,out,2);

  // s1: DCT expert chain
  cudaStreamWaitEvent(s1,evG1,0);
  cudaStreamWaitEvent(s1,evR,0);
  k_dct<<<dim3(128,32),256,0,s1>>>();
  k_lngemm<<<dim3(64,2,32),256,0,s1>>>(olw,olb,og,ob,out,0);
  cudaEventRecord(evC,s1);

  // join
  cudaStreamWaitEvent(0,evC,0);
  cudaStreamWaitEvent(0,evS2,0);
}